// round 17
// baseline (speedup 1.0000x reference)
#include <cuda_runtime.h>
#include <cuda_fp16.h>
#include <cstdint>

#define IN_CH   768
#define OUT_ROW 1536
#define BM      128
#define BN      128
#define NCHUNK  12          // 768/64
#define NT      1536        // tiles: 128 mtile * 4 ntile * 3 mod
#define GRID_P  444         // 148 SMs * 3 CTAs

// smem: [0,512) biasCur | [512,1024) biasNxt | [1024,1028) nextT | stages @2048
#define STGB     32768
#define SM_STG(s) (2048 + (s)*STGB)
#define OFF_B    16384
#define SMEM_TOTAL (2048 + 2*STGB)   // 67584 -> 3 CTAs/SM

#define SWZ(o) ((o) ^ (((o) >> 3) & 0x70))

// Pre-converted fp16 weights, layout == smem B block:
// [mod 3][ntile 4][kchunk 12][128 rows][128 B]
__device__ __align__(128) unsigned char g_Bscr[3*4*12*16384];
__device__ int g_ctr;    // work-stealing counter (reset by conv kernel)

static __device__ __forceinline__ uint32_t s2u(const void* p) {
    uint32_t a;
    asm("{ .reg .u64 t; cvta.to.shared.u64 t, %1; cvt.u32.u64 %0, t; }" : "=r"(a) : "l"(p));
    return a;
}
static __device__ __forceinline__ void ldsm4(uint32_t* r, uint32_t addr) {
    asm volatile("ldmatrix.sync.aligned.m8n8.x4.shared.b16 {%0,%1,%2,%3}, [%4];"
                 : "=r"(r[0]), "=r"(r[1]), "=r"(r[2]), "=r"(r[3]) : "r"(addr));
}
static __device__ __forceinline__ void mma16816(float* c, const uint32_t* a, const uint32_t* b) {
    asm volatile("mma.sync.aligned.m16n8k16.row.col.f32.f16.f16.f32 "
                 "{%0,%1,%2,%3}, {%4,%5,%6,%7}, {%8,%9}, {%0,%1,%2,%3};"
                 : "+f"(c[0]), "+f"(c[1]), "+f"(c[2]), "+f"(c[3])
                 : "r"(a[0]), "r"(a[1]), "r"(a[2]), "r"(a[3]), "r"(b[0]), "r"(b[1]));
}
static __device__ __forceinline__ void cp16(uint32_t dst, const void* src) {
    asm volatile("cp.async.cg.shared.global [%0], [%1], 16;" :: "r"(dst), "l"(src) : "memory");
}
#define CP_COMMIT asm volatile("cp.async.commit_group;" ::: "memory")
#define CP_WAIT0  asm volatile("cp.async.wait_group 0;" ::: "memory")

// ============ kernel 0: weight conversion (fp16 rn, swizzled) + counter reset ============
__global__ __launch_bounds__(256)
void caps_convw(const float* __restrict__ w_img,
                const float* __restrict__ w_capt,
                const float* __restrict__ w_dct)
{
    if (blockIdx.x == 0 && threadIdx.x == 0) g_ctr = GRID_P;
    int gt  = blockIdx.x * 256 + threadIdx.x;     // [0, 147456)
    int mod = gt / 49152;
    int r   = gt % 49152;
    int n   = r / 96;
    int k8  = r % 96;
    const float* W = (mod == 0) ? w_img : (mod == 1) ? w_capt : w_dct;
    int wrow = ((n & 7) << 6) | (n >> 3);         // W row for col n = r*8 + c
    const float4* src = (const float4*)(W + (size_t)wrow * IN_CH + k8 * 8);
    float4 p = src[0], q = src[1];
    __half2 h0 = __float22half2_rn(make_float2(p.x, p.y));
    __half2 h1 = __float22half2_rn(make_float2(p.z, p.w));
    __half2 h2 = __float22half2_rn(make_float2(q.x, q.y));
    __half2 h3 = __float22half2_rn(make_float2(q.z, q.w));
    int ntile = n >> 7, rloc = n & 127;
    int kch = k8 >> 3, cell = k8 & 7;
    uint32_t off = SWZ((uint32_t)(rloc * 128 + cell * 16));
    unsigned char* dst = g_Bscr + (size_t)((mod * 4 + ntile) * 12 + kch) * 16384 + off;
    *(uint4*)dst = make_uint4(*(uint32_t*)&h0, *(uint32_t*)&h1, *(uint32_t*)&h2, *(uint32_t*)&h3);
}

// tile decode
static __device__ __forceinline__ void decode_tile(int t, const float* const* Xs,
    const float*& xA, const unsigned char*& bG, int& b0, int& n0, int& mod)
{
    mod = t / 512;
    int rem = t - mod * 512;
    int mtile = rem >> 2, ntile = rem & 3;
    b0 = mtile * BM;
    n0 = ntile * BN;
    xA = Xs[mod] + (size_t)b0 * IN_CH;
    bG = g_Bscr + (size_t)((mod * 4 + ntile) * 12) * 16384;
}

// A producer: fp32 gmem -> fp16 swizzled smem, coalesced (16 lanes per row)
static __device__ __forceinline__ void produceA(unsigned char* stage, const float* xA,
                                                int kcol, int tid)
{
    const int l16 = tid & 15;          // 16B column within row
    const int rb  = tid >> 4;          // row base 0..7
    const float* src0 = xA + kcol + l16 * 4;
    const uint32_t off0 = SWZ((uint32_t)(((l16 >> 1) * 16))) ;  // cell part (row added per pass)
    #pragma unroll 4
    for (int p = 0; p < 16; ++p) {
        int row = p * 8 + rb;
        float4 v = *(const float4*)(src0 + (size_t)row * IN_CH);
        __half2 h0 = __float22half2_rn(make_float2(v.x, v.y));
        __half2 h1 = __float22half2_rn(make_float2(v.z, v.w));
        uint32_t off = SWZ((uint32_t)(row * 128 + (l16 >> 1) * 16)) + (uint32_t)((l16 & 1) * 8);
        *(uint2*)(stage + off) = make_uint2(*(uint32_t*)&h0, *(uint32_t*)&h1);
    }
    (void)off0;
}

// ============ kernel 1: persistent fused-convert GEMM + bias + squash ============
// 4 warps, warp tile 64x64, 3 CTAs/SM, 2-stage pipeline, atomic work-stealing
__global__ __launch_bounds__(128, 3)
void caps_gemm(const float* __restrict__ x_img,
               const float* __restrict__ x_capt,
               const float* __restrict__ x_dct,
               const float* __restrict__ b_img,
               const float* __restrict__ b_capt,
               const float* __restrict__ b_dct,
               float* __restrict__ out)
{
    extern __shared__ __align__(1024) unsigned char smem[];
    const uint32_t sb = s2u(smem);
    float* biasCur = (float*)smem;
    float* biasNxt = (float*)(smem + 512);
    volatile int* nextTS = (volatile int*)(smem + 1024);

    const float* Xs[3] = { x_img, x_capt, x_dct };

    const int tid  = threadIdx.x;
    const int lane = tid & 31;
    const int w    = tid >> 5;
    const int wm   = w & 1;
    const int wn   = w >> 1;

    const uint32_t aXor  = (uint32_t)((lane & 7) << 4);
    const uint32_t aRowB = (uint32_t)((wm * 64 + (lane & 15)) * 128);
    const uint32_t aCell = (uint32_t)(((lane >> 4) & 1) * 16);
    const uint32_t bXor  = aXor;
    const uint32_t bRowB = (uint32_t)((wn * 64 + (lane & 7) + ((lane & 16) ? 8 : 0)) * 128);
    const uint32_t bCell = (uint32_t)((lane & 8) ? 16 : 0);

    int t = blockIdx.x;
    const float* xA; const unsigned char* bG;
    int b0, n0, mod;
    decode_tile(t, Xs, xA, bG, b0, n0, mod);
    {
        const float* Bv = (mod == 0) ? b_img : (mod == 1) ? b_capt : b_dct;
        int n = n0 + tid; biasCur[tid] = Bv[((n & 7) << 6) + (n >> 3)];
    }

    // ---- prologue: stage 0 <- chunk 0 ----
    {
        uint32_t dst = sb + SM_STG(0) + OFF_B;
        #pragma unroll
        for (int j = 0; j < 8; ++j)
            cp16(dst + tid * 16 + j * 2048, bG + tid * 16 + j * 2048);
        CP_COMMIT;
        produceA(smem + SM_STG(0), xA, 0, tid);
    }
    CP_WAIT0;
    __syncthreads();

    int stage = 0;
    for (;;) {
        float acc[4][8][4];
        #pragma unroll
        for (int i = 0; i < 4; ++i)
            #pragma unroll
            for (int j = 0; j < 8; ++j)
                #pragma unroll
                for (int k = 0; k < 4; ++k) acc[i][j][k] = 0.f;

        int nt = NT;
        int nb0 = 0, nn0 = 0, nmod = 0;
        const float* xN = xA; const unsigned char* bN = bG;

        for (int i = 0; i < NCHUNK; ++i) {
            if (i == 0 && tid == 0) *nextTS = atomicAdd(&g_ctr, 1);

            // ---- B cp.async for next chunk (or next tile chunk 0) ----
            bool issued = false;
            const float* xSrc = xA; int kcolN = 0;
            if (i + 1 < NCHUNK) {
                uint32_t dst = sb + SM_STG(stage ^ 1) + OFF_B;
                const unsigned char* sbp = bG + (size_t)(i + 1) * 16384;
                #pragma unroll
                for (int j = 0; j < 8; ++j)
                    cp16(dst + tid * 16 + j * 2048, sbp + tid * 16 + j * 2048);
                CP_COMMIT;
                kcolN = (i + 1) * 64;
                issued = true;
            } else {
                nt = *nextTS;
                if (nt < NT) {
                    decode_tile(nt, Xs, xN, bN, nb0, nn0, nmod);
                    uint32_t dst = sb + SM_STG(stage ^ 1) + OFF_B;
                    #pragma unroll
                    for (int j = 0; j < 8; ++j)
                        cp16(dst + tid * 16 + j * 2048, bN + tid * 16 + j * 2048);
                    CP_COMMIT;
                    const float* Bv = (nmod == 0) ? b_img : (nmod == 1) ? b_capt : b_dct;
                    int n = nn0 + tid;
                    biasNxt[tid] = Bv[((n & 7) << 6) + (n >> 3)];
                    xSrc = xN; kcolN = 0;
                    issued = true;
                }
            }

            // ---- compute chunk i from current stage ----
            const uint32_t stg = sb + SM_STG(stage);
            #pragma unroll
            for (int st = 0; st < 4; ++st) {
                const uint32_t sx = (uint32_t)(st << 5);
                uint32_t af[4][4];
                #pragma unroll
                for (int mt = 0; mt < 4; ++mt)
                    ldsm4(af[mt], stg + aRowB + mt * 2048 + ((sx + aCell) ^ aXor));
                #pragma unroll
                for (int g = 0; g < 4; ++g) {
                    uint32_t bf[4];
                    ldsm4(bf, stg + OFF_B + bRowB + g * 2048 + ((sx + bCell) ^ bXor));
                    #pragma unroll
                    for (int half = 0; half < 2; ++half) {
                        const uint32_t* BH = &bf[half * 2];
                        #pragma unroll
                        for (int mt = 0; mt < 4; ++mt)
                            mma16816(acc[mt][2 * g + half], af[mt], BH);
                    }
                }
            }

            // ---- A convert-produce for the staged chunk (after compute; LDG hidden by other CTAs) ----
            if (issued) {
                produceA(smem + SM_STG(stage ^ 1), xSrc, kcolN, tid);
                CP_WAIT0;
                __syncthreads();
                stage ^= 1;
            }
        }

        // ---- epilogue: bias + squash (8-col group == one n8 tile) ----
        const int t4 = lane & 3, g8 = lane >> 2;
        #pragma unroll
        for (int mt = 0; mt < 4; ++mt) {
            const int row0 = b0 + wm * 64 + mt * 16 + g8;
            #pragma unroll
            for (int ntj = 0; ntj < 8; ++ntj) {
                float* c = acc[mt][ntj];
                const int cl = wn * 64 + ntj * 8 + 2 * t4;
                const float bx = biasCur[cl], by = biasCur[cl + 1];
                float u0 = c[0] + bx, u1 = c[1] + by;
                float u2 = c[2] + bx, u3 = c[3] + by;
                float s0 = u0 * u0 + u1 * u1;
                float s1 = u2 * u2 + u3 * u3;
                s0 += __shfl_xor_sync(0xffffffffu, s0, 1);
                s0 += __shfl_xor_sync(0xffffffffu, s0, 2);
                s1 += __shfl_xor_sync(0xffffffffu, s1, 1);
                s1 += __shfl_xor_sync(0xffffffffu, s1, 2);
                float sc0 = s0 / ((1.0f + s0) * sqrtf(s0 + 1e-7f));
                float sc1 = s1 / ((1.0f + s1) * sqrtf(s1 + 1e-7f));
                float* p0 = out + (size_t)row0 * OUT_ROW + mod * 512 + n0 + cl;
                float* p1 = p0 + 8 * OUT_ROW;
                *(float2*)p0 = make_float2(u0 * sc0, u1 * sc0);
                *(float2*)p1 = make_float2(u2 * sc1, u3 * sc1);
            }
        }

        if (nt >= NT) break;
        __syncthreads();                 // epilogue bias reads + nextTS reads done
        biasCur[tid] = biasNxt[tid];
        t = nt; xA = xN; bG = bN; b0 = nb0; n0 = nn0; mod = nmod;
        __syncthreads();                 // biasCur ready
    }
}

extern "C" void kernel_launch(void* const* d_in, const int* in_sizes, int n_in,
                              void* d_out, int out_size)
{
    const float* x_img  = (const float*)d_in[0];
    const float* x_capt = (const float*)d_in[1];
    const float* x_dct  = (const float*)d_in[2];
    const float* w_img  = (const float*)d_in[3];
    const float* b_img  = (const float*)d_in[4];
    const float* w_capt = (const float*)d_in[5];
    const float* b_capt = (const float*)d_in[6];
    const float* w_dct  = (const float*)d_in[7];
    const float* b_dct  = (const float*)d_in[8];
    float* out = (float*)d_out;

    cudaFuncSetAttribute(caps_gemm, cudaFuncAttributeMaxDynamicSharedMemorySize, SMEM_TOTAL);

    caps_convw<<<576, 256>>>(w_img, w_capt, w_dct);   // weights + g_ctr reset

    caps_gemm<<<GRID_P, 128, SMEM_TOTAL>>>(x_img, x_capt, x_dct,
                                           b_img, b_capt, b_dct, out);
}